// round 13
// baseline (speedup 1.0000x reference)
#include <cuda_runtime.h>
#include <cuda_bf16.h>
#include <math.h>

#define SEQ   8192
#define EMB   256
#define HID   128      // per-direction hidden
#define GATES 512      // 4*HID
#define NTAG  14
#define START 12
#define STOP  13
#define NEG   (-10000.0f)

// ---------------- scratch (device globals; no allocation) ----------------
__device__ float d_pre[2][SEQ][GATES];      // 32 MB: input projection + biases
__device__ float d_h[2][SEQ][HID];          // 8 MB
__device__ float d_feats[SEQ * 16];         // padded stride 16

// ---------------- PTX helpers ---------------------------------------------
__device__ __forceinline__ unsigned smem_u32(const void* p) {
    unsigned a;
    asm("{ .reg .u64 t; cvta.to.shared.u64 t, %1; cvt.u32.u64 %0, t; }"
        : "=r"(a) : "l"(p));
    return a;
}
__device__ __forceinline__ unsigned mapa_u32(unsigned a, unsigned rank) {
    unsigned r;
    asm("mapa.shared::cluster.u32 %0, %1, %2;" : "=r"(r) : "r"(a), "r"(rank));
    return r;
}
__device__ __forceinline__ void st_remote_f32(unsigned addr, float v) {
    asm volatile("st.shared::cluster.f32 [%0], %1;" :: "r"(addr), "f"(v) : "memory");
}
__device__ __forceinline__ void mbar_init(unsigned addr, unsigned cnt) {
    asm volatile("mbarrier.init.shared.b64 [%0], %1;" :: "r"(addr), "r"(cnt) : "memory");
}
__device__ __forceinline__ void mbar_arrive_remote(unsigned addr) {
    asm volatile("mbarrier.arrive.release.cluster.shared::cluster.b64 _, [%0];"
                 :: "r"(addr) : "memory");
}
__device__ __forceinline__ void mbar_wait_acq_cluster(unsigned addr, unsigned parity) {
    asm volatile(
        "{\n\t"
        ".reg .pred P;\n\t"
        "WL%=:\n\t"
        "mbarrier.try_wait.parity.acquire.cluster.shared::cta.b64 P, [%0], %1, 0x989680;\n\t"
        "@P bra WD%=;\n\t"
        "bra WL%=;\n\t"
        "WD%=:\n\t"
        "}"
        :: "r"(addr), "r"(parity) : "memory");
}
__device__ __forceinline__ void cluster_sync_() {
    asm volatile("barrier.cluster.arrive.aligned;" ::: "memory");
    asm volatile("barrier.cluster.wait.aligned;" ::: "memory");
}

// MUFU.TANH (sm_75+): single-instruction tanh, lat ~16
__device__ __forceinline__ float tanh_mufu(float x) {
    float y;
    asm("tanh.approx.f32 %0, %1;" : "=f"(y) : "f"(x));
    return y;
}
// sigmoid via MUFU.TANH: 1 MUFU + 1 FMA
__device__ __forceinline__ float sig_mufu(float x) {
    return fmaf(0.5f, tanh_mufu(0.5f * x), 0.5f);
}

// ---------------- kernel 1: input projection GEMM -------------------------
__global__ void __launch_bounds__(256) prep_kernel(
    const int* __restrict__ sent, const float* __restrict__ emb,
    const float* __restrict__ wih_f, const float* __restrict__ bih_f, const float* __restrict__ bhh_f,
    const float* __restrict__ wih_b, const float* __restrict__ bih_b, const float* __restrict__ bhh_b)
{
    const int dir = blockIdx.z;
    const float* wih = dir ? wih_b : wih_f;
    const float* bih = dir ? bih_b : bih_f;
    const float* bhh = dir ? bhh_b : bhh_f;
    const int t0 = blockIdx.x * 64;
    const int r0 = blockIdx.y * 64;

    __shared__ float xs[64][65];
    __shared__ float ws[64][65];
    __shared__ int   sidx[64];

    const int tid = threadIdx.x;
    if (tid < 64) {
        int t = t0 + tid;
        sidx[tid] = sent[dir ? (SEQ - 1 - t) : t];
    }

    const int tx = tid & 15;
    const int ty = tid >> 4;
    float acc[4][4];
    #pragma unroll
    for (int i = 0; i < 4; i++)
        #pragma unroll
        for (int j = 0; j < 4; j++) acc[i][j] = 0.f;

    for (int kc = 0; kc < EMB; kc += 64) {
        __syncthreads();
        #pragma unroll
        for (int e = 0; e < 16; e++) {
            int lin = e * 256 + tid;
            int kk  = lin & 63;
            int row = lin >> 6;
            xs[kk][row] = emb[(size_t)sidx[row] * EMB + kc + kk];
            ws[kk][row] = wih[(size_t)(r0 + row) * EMB + kc + kk];
        }
        __syncthreads();
        #pragma unroll 8
        for (int kk = 0; kk < 64; kk++) {
            float xv[4], wv[4];
            #pragma unroll
            for (int i = 0; i < 4; i++) xv[i] = xs[kk][tx + 16 * i];
            #pragma unroll
            for (int j = 0; j < 4; j++) wv[j] = ws[kk][ty + 16 * j];
            #pragma unroll
            for (int i = 0; i < 4; i++)
                #pragma unroll
                for (int j = 0; j < 4; j++) acc[i][j] += xv[i] * wv[j];
        }
    }

    #pragma unroll
    for (int i = 0; i < 4; i++) {
        int t = t0 + tx + 16 * i;
        #pragma unroll
        for (int j = 0; j < 4; j++) {
            int r = r0 + ty + 16 * j;
            d_pre[dir][t][r] = acc[i][j] + bih[r] + bhh[r];
        }
    }
}

// ---------------- kernel 2: clustered LSTM (champion sync structure) -------
// 4 CTAs, clusters of 2. blockIdx.x: {0,1}=dir0, {2,3}=dir1.
// 256 threads/CTA, one full gate row per thread (128 weights in regs),
// CTA owns 64 hidden units; smem-acts combine; 64 remote arrives/step;
// cluster-scope acquire wait. CHANGES vs 8863 champion: MUFU.TANH
// activations; 8 matvec accumulators (shorter dependent chains).
__global__ void __launch_bounds__(256, 1) __cluster_dims__(2, 1, 1)
lstm_kernel(const float* __restrict__ whh_f, const float* __restrict__ whh_b)
{
    const int dir  = blockIdx.x >> 1;
    const int rank = blockIdx.x & 1;
    const float* __restrict__ whh = dir ? whh_b : whh_f;
    const float* __restrict__ pre  = &d_pre[dir][0][0];
    float* __restrict__ hout = &d_h[dir][0][0];

    __shared__ __align__(16) float hsm[2][HID];   // double-buffered full h
    __shared__ float acts[256];
    __shared__ unsigned long long mbar[2];

    const int tid = threadIdx.x;
    const int g   = tid >> 6;                 // gate 0..3 (i,f,g,o) - warp-uniform
    const int j   = tid & 63;                 // local unit index
    const int u   = rank * 64 + j;            // global hidden unit
    const int row = g * 128 + u;              // global gate row

    // scalar register weights: wA = my-half columns, wB = peer-half columns
    float wA[64], wB[64];
    {
        const float* wr = &whh[(size_t)row * HID];
        const int la = rank * 64, lb = (rank ^ 1) * 64;
        #pragma unroll
        for (int k = 0; k < 64; k += 4) {
            float4 va = *(const float4*)&wr[la + k];
            wA[k] = va.x; wA[k+1] = va.y; wA[k+2] = va.z; wA[k+3] = va.w;
            float4 vb = *(const float4*)&wr[lb + k];
            wB[k] = vb.x; wB[k+1] = vb.y; wB[k+2] = vb.z; wB[k+3] = vb.w;
        }
    }

    const unsigned h_loc  = smem_u32(&hsm[0][0]);
    const unsigned mb_loc = smem_u32(&mbar[0]);
    const unsigned peer   = rank ^ 1;
    const unsigned h_rm   = mapa_u32(h_loc, peer);
    const unsigned mb_rm  = mapa_u32(mb_loc, peer);

    if (tid < 2) mbar_init(mb_loc + tid * 8, 64);  // 64 updater-thread arrives
    __syncthreads();
    cluster_sync_();                               // mbarriers visible cluster-wide

    float c = 0.f;
    float pre_cur = pre[row];

    // ---- t = 0 peel: h=0, gates = pre ----
    {
        acts[tid] = (g == 2) ? tanh_mufu(pre_cur) : sig_mufu(pre_cur);
        pre_cur = pre[GATES + row];           // prefetch t=1
        __syncthreads();
        if (tid < 64) {
            float iv = acts[tid], fv = acts[64 + tid], gv = acts[128 + tid], ov = acts[192 + tid];
            c = fv * c + iv * gv;
            float h = ov * tanh_mufu(c);
            hsm[1][u] = h;                    // buffer for t=1
            hout[u] = h;                      // hout[0][u]
            st_remote_f32(h_rm + (unsigned)(HID + u) * 4u, h);
            mbar_arrive_remote(mb_rm + 8);    // mbar[1]
        }
        __syncthreads();
    }

    // ---- main loop t = 1 .. SEQ-1 ----
    for (int t = 1; t < SEQ; t++) {
        float pre_nxt = 0.f;
        if (t + 1 < SEQ) pre_nxt = pre[(size_t)(t + 1) * GATES + row];

        const int b = t & 1;
        float a0 = 0.f, a1 = 0.f, a2 = 0.f, a3 = 0.f;
        float a4 = 0.f, a5 = 0.f, a6 = 0.f, a7 = 0.f;

        // local half (written by this CTA last step)
        {
            const float* hb = &hsm[b][rank * 64];
            #pragma unroll
            for (int k = 0; k < 64; k += 8) {
                float4 h0 = *(const float4*)&hb[k];
                float4 h1 = *(const float4*)&hb[k + 4];
                a0 += wA[k+0] * h0.x;
                a1 += wA[k+1] * h0.y;
                a2 += wA[k+2] * h0.z;
                a3 += wA[k+3] * h0.w;
                a4 += wA[k+4] * h1.x;
                a5 += wA[k+5] * h1.y;
                a6 += wA[k+6] * h1.z;
                a7 += wA[k+7] * h1.w;
            }
        }
        // wait for peer's half of h(t); parity = ((t-1)>>1)&1 for both buffers
        mbar_wait_acq_cluster(mb_loc + b * 8, ((t - 1) >> 1) & 1);
        {
            const float* hb = &hsm[b][(rank ^ 1) * 64];
            #pragma unroll
            for (int k = 0; k < 64; k += 8) {
                float4 h0 = *(const float4*)&hb[k];
                float4 h1 = *(const float4*)&hb[k + 4];
                a0 += wB[k+0] * h0.x;
                a1 += wB[k+1] * h0.y;
                a2 += wB[k+2] * h0.z;
                a3 += wB[k+3] * h0.w;
                a4 += wB[k+4] * h1.x;
                a5 += wB[k+5] * h1.y;
                a6 += wB[k+6] * h1.z;
                a7 += wB[k+7] * h1.w;
            }
        }
        float acc = pre_cur + (((a0 + a1) + (a2 + a3)) + ((a4 + a5) + (a6 + a7)));

        acts[tid] = (g == 2) ? tanh_mufu(acc) : sig_mufu(acc);
        __syncthreads();

        if (tid < 64) {
            float iv = acts[tid], fv = acts[64 + tid], gv = acts[128 + tid], ov = acts[192 + tid];
            c = fv * c + iv * gv;
            float h = ov * tanh_mufu(c);
            const int nb = (t + 1) & 1;
            hsm[nb][u] = h;
            hout[(size_t)t * HID + u] = h;
            if (t < SEQ - 1) {
                st_remote_f32(h_rm + (unsigned)(nb * HID + u) * 4u, h);
                mbar_arrive_remote(mb_rm + nb * 8);
            }
        }
        __syncthreads();
        pre_cur = pre_nxt;
    }

    cluster_sync_();
}

// ---------------- kernel 3: tag feats ------------------------------------
__global__ void __launch_bounds__(256) feats_kernel(
    const float* __restrict__ wtag, const float* __restrict__ btag)
{
    const int tid = threadIdx.x;
    const int n  = tid & 15;
    const int tl = tid >> 4;
    const int t  = blockIdx.x * 16 + tl;
    if (n >= NTAG) return;

    const float* __restrict__ hf = &d_h[0][t][0];
    const float* __restrict__ hb = &d_h[1][SEQ - 1 - t][0];
    const float* __restrict__ w  = &wtag[n * 256];

    float acc = btag[n];
    #pragma unroll 8
    for (int jj = 0; jj < HID; jj += 4) {
        float4 h4 = *(const float4*)&hf[jj];
        float4 w4 = *(const float4*)&w[jj];
        acc += h4.x * w4.x + h4.y * w4.y + h4.z * w4.z + h4.w * w4.w;
    }
    #pragma unroll 8
    for (int jj = 0; jj < HID; jj += 4) {
        float4 h4 = *(const float4*)&hb[jj];
        float4 w4 = *(const float4*)&w[HID + jj];
        acc += h4.x * w4.x + h4.y * w4.y + h4.z * w4.z + h4.w * w4.w;
    }
    d_feats[t * 16 + n] = acc;
}

// ---------------- kernel 4: Viterbi, register-resident fv ------------------
#define VCHUNK 512
#define NCHUNK (SEQ / VCHUNK)
#define VIT_SMEM (SEQ * 16 + 2 * VCHUNK * 16 * 4 + 64)

#define CMB(va, ia, vb, ib) { bool _gt = ((vb) > (va)); (va) = _gt ? (vb) : (va); (ia) = _gt ? (ib) : (ia); }

__global__ void __launch_bounds__(256, 1) viterbi_kernel(
    const float* __restrict__ trans, float* __restrict__ out)
{
    extern __shared__ unsigned char vsm[];
    unsigned char* bp = vsm;                                  // [SEQ][16]
    float* fbuf = (float*)(vsm + SEQ * 16);                   // [2][VCHUNK*16]
    float* fout = fbuf + 2 * VCHUNK * 16;                     // [16]

    const int tid  = threadIdx.x;
    const int warp = tid >> 5;
    const int lane = tid & 31;

    for (int i = tid; i < VCHUNK * 16; i += 256) fbuf[i] = d_feats[i];

    float fv = (lane == START) ? 0.f : NEG;
    float tr[NTAG];
    #pragma unroll
    for (int p = 0; p < NTAG; p++)
        tr[p] = (lane < NTAG) ? trans[lane * NTAG + p] : 0.f;
    __syncthreads();

    for (int ch = 0; ch < NCHUNK; ch++) {
        const int buf = ch & 1;
        if (warp > 0) {
            if (ch + 1 < NCHUNK) {
                const int nbuf = buf ^ 1;
                for (int i = tid - 32; i < VCHUNK * 16; i += 224)
                    fbuf[nbuf * VCHUNK * 16 + i] = d_feats[(ch + 1) * VCHUNK * 16 + i];
            }
        } else {
            const float* fb = fbuf + buf * VCHUNK * 16;
            for (int s = 0; s < VCHUNK; s++) {
                const int t = ch * VCHUNK + s;
                float sv[NTAG];
                #pragma unroll
                for (int p = 0; p < NTAG; p++)
                    sv[p] = __shfl_sync(0xffffffffu, fv, p) + tr[p];
                float v[7]; int ix[7];
                #pragma unroll
                for (int k = 0; k < 7; k++) {
                    bool gt = sv[2*k+1] > sv[2*k];
                    v[k]  = gt ? sv[2*k+1] : sv[2*k];
                    ix[k] = gt ? (2*k+1) : (2*k);
                }
                CMB(v[0], ix[0], v[1], ix[1]);
                CMB(v[2], ix[2], v[3], ix[3]);
                CMB(v[4], ix[4], v[5], ix[5]);
                CMB(v[0], ix[0], v[2], ix[2]);
                CMB(v[4], ix[4], v[6], ix[6]);
                CMB(v[0], ix[0], v[4], ix[4]);
                if (lane < NTAG) {
                    fv = v[0] + fb[s * 16 + lane];
                    bp[t * 16 + lane] = (unsigned char)ix[0];
                }
            }
        }
        __syncthreads();
    }

    if (warp == 0 && lane < NTAG) fout[lane] = fv;
    __syncthreads();

    if (tid == 0) {
        float best = fout[0] + trans[STOP * NTAG + 0]; int barg = 0;
        #pragma unroll
        for (int p = 1; p < NTAG; p++) {
            float sc = fout[p] + trans[STOP * NTAG + p];
            if (sc > best) { best = sc; barg = p; }
        }
        out[0] = best;
        int tag = barg;
        for (int t = SEQ - 1; t >= 0; t--) {
            out[1 + t] = (float)tag;
            tag = bp[t * 16 + tag];
        }
    }
}

// ---------------- launch ---------------------------------------------------
extern "C" void kernel_launch(void* const* d_in, const int* in_sizes, int n_in,
                              void* d_out, int out_size)
{
    const int*   sent  = (const int*)  d_in[0];
    const float* emb   = (const float*)d_in[1];
    const float* wih_f = (const float*)d_in[2];
    const float* whh_f = (const float*)d_in[3];
    const float* bih_f = (const float*)d_in[4];
    const float* bhh_f = (const float*)d_in[5];
    const float* wih_b = (const float*)d_in[6];
    const float* whh_b = (const float*)d_in[7];
    const float* bih_b = (const float*)d_in[8];
    const float* bhh_b = (const float*)d_in[9];
    const float* wtag  = (const float*)d_in[10];
    const float* btag  = (const float*)d_in[11];
    const float* trans = (const float*)d_in[12];
    float* out = (float*)d_out;

    cudaFuncSetAttribute(viterbi_kernel, cudaFuncAttributeMaxDynamicSharedMemorySize, VIT_SMEM);

    prep_kernel<<<dim3(SEQ / 64, GATES / 64, 2), 256>>>(
        sent, emb, wih_f, bih_f, bhh_f, wih_b, bih_b, bhh_b);
    lstm_kernel<<<4, 256>>>(whh_f, whh_b);
    feats_kernel<<<SEQ / 16, 256>>>(wtag, btag);
    viterbi_kernel<<<1, 256, VIT_SMEM>>>(trans, out);
}

// round 14
// speedup vs baseline: 1.0030x; 1.0030x over previous
#include <cuda_runtime.h>
#include <cuda_bf16.h>
#include <math.h>

#define SEQ   8192
#define EMB   256
#define HID   128      // per-direction hidden
#define GATES 512      // 4*HID
#define NTAG  14
#define START 12
#define STOP  13
#define NEG   (-10000.0f)

// ---------------- scratch (device globals; no allocation) ----------------
__device__ float d_pre[2][SEQ][GATES];      // 32 MB: input projection + biases
__device__ float d_h[2][SEQ][HID];          // 8 MB
__device__ float d_feats[SEQ * 16];         // padded stride 16

// ---------------- PTX helpers ---------------------------------------------
__device__ __forceinline__ unsigned smem_u32(const void* p) {
    unsigned a;
    asm("{ .reg .u64 t; cvta.to.shared.u64 t, %1; cvt.u32.u64 %0, t; }"
        : "=r"(a) : "l"(p));
    return a;
}
__device__ __forceinline__ unsigned mapa_u32(unsigned a, unsigned rank) {
    unsigned r;
    asm("mapa.shared::cluster.u32 %0, %1, %2;" : "=r"(r) : "r"(a), "r"(rank));
    return r;
}
__device__ __forceinline__ void st_remote_f32(unsigned addr, float v) {
    asm volatile("st.shared::cluster.f32 [%0], %1;" :: "r"(addr), "f"(v) : "memory");
}
__device__ __forceinline__ void mbar_init(unsigned addr, unsigned cnt) {
    asm volatile("mbarrier.init.shared.b64 [%0], %1;" :: "r"(addr), "r"(cnt) : "memory");
}
__device__ __forceinline__ void mbar_arrive_remote(unsigned addr) {
    asm volatile("mbarrier.arrive.release.cluster.shared::cluster.b64 _, [%0];"
                 :: "r"(addr) : "memory");
}
__device__ __forceinline__ void mbar_wait_acq_cluster(unsigned addr, unsigned parity) {
    asm volatile(
        "{\n\t"
        ".reg .pred P;\n\t"
        "WL%=:\n\t"
        "mbarrier.try_wait.parity.acquire.cluster.shared::cta.b64 P, [%0], %1, 0x989680;\n\t"
        "@P bra WD%=;\n\t"
        "bra WL%=;\n\t"
        "WD%=:\n\t"
        "}"
        :: "r"(addr), "r"(parity) : "memory");
}
__device__ __forceinline__ void cluster_sync_() {
    asm volatile("barrier.cluster.arrive.aligned;" ::: "memory");
    asm volatile("barrier.cluster.wait.aligned;" ::: "memory");
}

// MUFU.TANH (sm_75+): single-instruction tanh, lat ~16
__device__ __forceinline__ float tanh_mufu(float x) {
    float y;
    asm("tanh.approx.f32 %0, %1;" : "=f"(y) : "f"(x));
    return y;
}
// sigmoid via MUFU.TANH: 1 MUFU + 1 FMA
__device__ __forceinline__ float sig_mufu(float x) {
    return fmaf(0.5f, tanh_mufu(0.5f * x), 0.5f);
}

// ---------------- kernel 1: input projection GEMM -------------------------
__global__ void __launch_bounds__(256) prep_kernel(
    const int* __restrict__ sent, const float* __restrict__ emb,
    const float* __restrict__ wih_f, const float* __restrict__ bih_f, const float* __restrict__ bhh_f,
    const float* __restrict__ wih_b, const float* __restrict__ bih_b, const float* __restrict__ bhh_b)
{
    const int dir = blockIdx.z;
    const float* wih = dir ? wih_b : wih_f;
    const float* bih = dir ? bih_b : bih_f;
    const float* bhh = dir ? bhh_b : bhh_f;
    const int t0 = blockIdx.x * 64;
    const int r0 = blockIdx.y * 64;

    __shared__ float xs[64][65];
    __shared__ float ws[64][65];
    __shared__ int   sidx[64];

    const int tid = threadIdx.x;
    if (tid < 64) {
        int t = t0 + tid;
        sidx[tid] = sent[dir ? (SEQ - 1 - t) : t];
    }

    const int tx = tid & 15;
    const int ty = tid >> 4;
    float acc[4][4];
    #pragma unroll
    for (int i = 0; i < 4; i++)
        #pragma unroll
        for (int j = 0; j < 4; j++) acc[i][j] = 0.f;

    for (int kc = 0; kc < EMB; kc += 64) {
        __syncthreads();
        #pragma unroll
        for (int e = 0; e < 16; e++) {
            int lin = e * 256 + tid;
            int kk  = lin & 63;
            int row = lin >> 6;
            xs[kk][row] = emb[(size_t)sidx[row] * EMB + kc + kk];
            ws[kk][row] = wih[(size_t)(r0 + row) * EMB + kc + kk];
        }
        __syncthreads();
        #pragma unroll 8
        for (int kk = 0; kk < 64; kk++) {
            float xv[4], wv[4];
            #pragma unroll
            for (int i = 0; i < 4; i++) xv[i] = xs[kk][tx + 16 * i];
            #pragma unroll
            for (int j = 0; j < 4; j++) wv[j] = ws[kk][ty + 16 * j];
            #pragma unroll
            for (int i = 0; i < 4; i++)
                #pragma unroll
                for (int j = 0; j < 4; j++) acc[i][j] += xv[i] * wv[j];
        }
    }

    #pragma unroll
    for (int i = 0; i < 4; i++) {
        int t = t0 + tx + 16 * i;
        #pragma unroll
        for (int j = 0; j < 4; j++) {
            int r = r0 + ty + 16 * j;
            d_pre[dir][t][r] = acc[i][j] + bih[r] + bhh[r];
        }
    }
}

// ---------------- kernel 2: clustered LSTM (champion sync structure) -------
// 4 CTAs, clusters of 2. blockIdx.x: {0,1}=dir0, {2,3}=dir1.
// 256 threads/CTA, one full gate row per thread (128 weights in regs),
// CTA owns 64 hidden units; smem-acts combine; 64 remote arrives/step;
// cluster-scope acquire wait. CHANGES vs 8863 champion: MUFU.TANH
// activations; 8 matvec accumulators (shorter dependent chains).
__global__ void __launch_bounds__(256, 1) __cluster_dims__(2, 1, 1)
lstm_kernel(const float* __restrict__ whh_f, const float* __restrict__ whh_b)
{
    const int dir  = blockIdx.x >> 1;
    const int rank = blockIdx.x & 1;
    const float* __restrict__ whh = dir ? whh_b : whh_f;
    const float* __restrict__ pre  = &d_pre[dir][0][0];
    float* __restrict__ hout = &d_h[dir][0][0];

    __shared__ __align__(16) float hsm[2][HID];   // double-buffered full h
    __shared__ float acts[256];
    __shared__ unsigned long long mbar[2];

    const int tid = threadIdx.x;
    const int g   = tid >> 6;                 // gate 0..3 (i,f,g,o) - warp-uniform
    const int j   = tid & 63;                 // local unit index
    const int u   = rank * 64 + j;            // global hidden unit
    const int row = g * 128 + u;              // global gate row

    // scalar register weights: wA = my-half columns, wB = peer-half columns
    float wA[64], wB[64];
    {
        const float* wr = &whh[(size_t)row * HID];
        const int la = rank * 64, lb = (rank ^ 1) * 64;
        #pragma unroll
        for (int k = 0; k < 64; k += 4) {
            float4 va = *(const float4*)&wr[la + k];
            wA[k] = va.x; wA[k+1] = va.y; wA[k+2] = va.z; wA[k+3] = va.w;
            float4 vb = *(const float4*)&wr[lb + k];
            wB[k] = vb.x; wB[k+1] = vb.y; wB[k+2] = vb.z; wB[k+3] = vb.w;
        }
    }

    const unsigned h_loc  = smem_u32(&hsm[0][0]);
    const unsigned mb_loc = smem_u32(&mbar[0]);
    const unsigned peer   = rank ^ 1;
    const unsigned h_rm   = mapa_u32(h_loc, peer);
    const unsigned mb_rm  = mapa_u32(mb_loc, peer);

    if (tid < 2) mbar_init(mb_loc + tid * 8, 64);  // 64 updater-thread arrives
    __syncthreads();
    cluster_sync_();                               // mbarriers visible cluster-wide

    float c = 0.f;
    float pre_cur = pre[row];

    // ---- t = 0 peel: h=0, gates = pre ----
    {
        acts[tid] = (g == 2) ? tanh_mufu(pre_cur) : sig_mufu(pre_cur);
        pre_cur = pre[GATES + row];           // prefetch t=1
        __syncthreads();
        if (tid < 64) {
            float iv = acts[tid], fv = acts[64 + tid], gv = acts[128 + tid], ov = acts[192 + tid];
            c = fv * c + iv * gv;
            float h = ov * tanh_mufu(c);
            hsm[1][u] = h;                    // buffer for t=1
            hout[u] = h;                      // hout[0][u]
            st_remote_f32(h_rm + (unsigned)(HID + u) * 4u, h);
            mbar_arrive_remote(mb_rm + 8);    // mbar[1]
        }
        __syncthreads();
    }

    // ---- main loop t = 1 .. SEQ-1 ----
    for (int t = 1; t < SEQ; t++) {
        float pre_nxt = 0.f;
        if (t + 1 < SEQ) pre_nxt = pre[(size_t)(t + 1) * GATES + row];

        const int b = t & 1;
        float a0 = 0.f, a1 = 0.f, a2 = 0.f, a3 = 0.f;
        float a4 = 0.f, a5 = 0.f, a6 = 0.f, a7 = 0.f;

        // local half (written by this CTA last step)
        {
            const float* hb = &hsm[b][rank * 64];
            #pragma unroll
            for (int k = 0; k < 64; k += 8) {
                float4 h0 = *(const float4*)&hb[k];
                float4 h1 = *(const float4*)&hb[k + 4];
                a0 += wA[k+0] * h0.x;
                a1 += wA[k+1] * h0.y;
                a2 += wA[k+2] * h0.z;
                a3 += wA[k+3] * h0.w;
                a4 += wA[k+4] * h1.x;
                a5 += wA[k+5] * h1.y;
                a6 += wA[k+6] * h1.z;
                a7 += wA[k+7] * h1.w;
            }
        }
        // wait for peer's half of h(t); parity = ((t-1)>>1)&1 for both buffers
        mbar_wait_acq_cluster(mb_loc + b * 8, ((t - 1) >> 1) & 1);
        {
            const float* hb = &hsm[b][(rank ^ 1) * 64];
            #pragma unroll
            for (int k = 0; k < 64; k += 8) {
                float4 h0 = *(const float4*)&hb[k];
                float4 h1 = *(const float4*)&hb[k + 4];
                a0 += wB[k+0] * h0.x;
                a1 += wB[k+1] * h0.y;
                a2 += wB[k+2] * h0.z;
                a3 += wB[k+3] * h0.w;
                a4 += wB[k+4] * h1.x;
                a5 += wB[k+5] * h1.y;
                a6 += wB[k+6] * h1.z;
                a7 += wB[k+7] * h1.w;
            }
        }
        float acc = pre_cur + (((a0 + a1) + (a2 + a3)) + ((a4 + a5) + (a6 + a7)));

        acts[tid] = (g == 2) ? tanh_mufu(acc) : sig_mufu(acc);
        __syncthreads();

        if (tid < 64) {
            float iv = acts[tid], fv = acts[64 + tid], gv = acts[128 + tid], ov = acts[192 + tid];
            c = fv * c + iv * gv;
            float h = ov * tanh_mufu(c);
            const int nb = (t + 1) & 1;
            hsm[nb][u] = h;
            hout[(size_t)t * HID + u] = h;
            if (t < SEQ - 1) {
                st_remote_f32(h_rm + (unsigned)(nb * HID + u) * 4u, h);
                mbar_arrive_remote(mb_rm + nb * 8);
            }
        }
        __syncthreads();
        pre_cur = pre_nxt;
    }

    cluster_sync_();
}

// ---------------- kernel 3: tag feats ------------------------------------
__global__ void __launch_bounds__(256) feats_kernel(
    const float* __restrict__ wtag, const float* __restrict__ btag)
{
    const int tid = threadIdx.x;
    const int n  = tid & 15;
    const int tl = tid >> 4;
    const int t  = blockIdx.x * 16 + tl;
    if (n >= NTAG) return;

    const float* __restrict__ hf = &d_h[0][t][0];
    const float* __restrict__ hb = &d_h[1][SEQ - 1 - t][0];
    const float* __restrict__ w  = &wtag[n * 256];

    float acc = btag[n];
    #pragma unroll 8
    for (int jj = 0; jj < HID; jj += 4) {
        float4 h4 = *(const float4*)&hf[jj];
        float4 w4 = *(const float4*)&w[jj];
        acc += h4.x * w4.x + h4.y * w4.y + h4.z * w4.z + h4.w * w4.w;
    }
    #pragma unroll 8
    for (int jj = 0; jj < HID; jj += 4) {
        float4 h4 = *(const float4*)&hb[jj];
        float4 w4 = *(const float4*)&w[HID + jj];
        acc += h4.x * w4.x + h4.y * w4.y + h4.z * w4.z + h4.w * w4.w;
    }
    d_feats[t * 16 + n] = acc;
}

// ---------------- kernel 4: Viterbi, register-resident fv ------------------
#define VCHUNK 512
#define NCHUNK (SEQ / VCHUNK)
#define VIT_SMEM (SEQ * 16 + 2 * VCHUNK * 16 * 4 + 64)

#define CMB(va, ia, vb, ib) { bool _gt = ((vb) > (va)); (va) = _gt ? (vb) : (va); (ia) = _gt ? (ib) : (ia); }

__global__ void __launch_bounds__(256, 1) viterbi_kernel(
    const float* __restrict__ trans, float* __restrict__ out)
{
    extern __shared__ unsigned char vsm[];
    unsigned char* bp = vsm;                                  // [SEQ][16]
    float* fbuf = (float*)(vsm + SEQ * 16);                   // [2][VCHUNK*16]
    float* fout = fbuf + 2 * VCHUNK * 16;                     // [16]

    const int tid  = threadIdx.x;
    const int warp = tid >> 5;
    const int lane = tid & 31;

    for (int i = tid; i < VCHUNK * 16; i += 256) fbuf[i] = d_feats[i];

    float fv = (lane == START) ? 0.f : NEG;
    float tr[NTAG];
    #pragma unroll
    for (int p = 0; p < NTAG; p++)
        tr[p] = (lane < NTAG) ? trans[lane * NTAG + p] : 0.f;
    __syncthreads();

    for (int ch = 0; ch < NCHUNK; ch++) {
        const int buf = ch & 1;
        if (warp > 0) {
            if (ch + 1 < NCHUNK) {
                const int nbuf = buf ^ 1;
                for (int i = tid - 32; i < VCHUNK * 16; i += 224)
                    fbuf[nbuf * VCHUNK * 16 + i] = d_feats[(ch + 1) * VCHUNK * 16 + i];
            }
        } else {
            const float* fb = fbuf + buf * VCHUNK * 16;
            for (int s = 0; s < VCHUNK; s++) {
                const int t = ch * VCHUNK + s;
                float sv[NTAG];
                #pragma unroll
                for (int p = 0; p < NTAG; p++)
                    sv[p] = __shfl_sync(0xffffffffu, fv, p) + tr[p];
                float v[7]; int ix[7];
                #pragma unroll
                for (int k = 0; k < 7; k++) {
                    bool gt = sv[2*k+1] > sv[2*k];
                    v[k]  = gt ? sv[2*k+1] : sv[2*k];
                    ix[k] = gt ? (2*k+1) : (2*k);
                }
                CMB(v[0], ix[0], v[1], ix[1]);
                CMB(v[2], ix[2], v[3], ix[3]);
                CMB(v[4], ix[4], v[5], ix[5]);
                CMB(v[0], ix[0], v[2], ix[2]);
                CMB(v[4], ix[4], v[6], ix[6]);
                CMB(v[0], ix[0], v[4], ix[4]);
                if (lane < NTAG) {
                    fv = v[0] + fb[s * 16 + lane];
                    bp[t * 16 + lane] = (unsigned char)ix[0];
                }
            }
        }
        __syncthreads();
    }

    if (warp == 0 && lane < NTAG) fout[lane] = fv;
    __syncthreads();

    if (tid == 0) {
        float best = fout[0] + trans[STOP * NTAG + 0]; int barg = 0;
        #pragma unroll
        for (int p = 1; p < NTAG; p++) {
            float sc = fout[p] + trans[STOP * NTAG + p];
            if (sc > best) { best = sc; barg = p; }
        }
        out[0] = best;
        int tag = barg;
        for (int t = SEQ - 1; t >= 0; t--) {
            out[1 + t] = (float)tag;
            tag = bp[t * 16 + tag];
        }
    }
}

// ---------------- launch ---------------------------------------------------
extern "C" void kernel_launch(void* const* d_in, const int* in_sizes, int n_in,
                              void* d_out, int out_size)
{
    const int*   sent  = (const int*)  d_in[0];
    const float* emb   = (const float*)d_in[1];
    const float* wih_f = (const float*)d_in[2];
    const float* whh_f = (const float*)d_in[3];
    const float* bih_f = (const float*)d_in[4];
    const float* bhh_f = (const float*)d_in[5];
    const float* wih_b = (const float*)d_in[6];
    const float* whh_b = (const float*)d_in[7];
    const float* bih_b = (const float*)d_in[8];
    const float* bhh_b = (const float*)d_in[9];
    const float* wtag  = (const float*)d_in[10];
    const float* btag  = (const float*)d_in[11];
    const float* trans = (const float*)d_in[12];
    float* out = (float*)d_out;

    cudaFuncSetAttribute(viterbi_kernel, cudaFuncAttributeMaxDynamicSharedMemorySize, VIT_SMEM);

    prep_kernel<<<dim3(SEQ / 64, GATES / 64, 2), 256>>>(
        sent, emb, wih_f, bih_f, bhh_f, wih_b, bih_b, bhh_b);
    lstm_kernel<<<4, 256>>>(whh_f, whh_b);
    feats_kernel<<<SEQ / 16, 256>>>(wtag, btag);
    viterbi_kernel<<<1, 256, VIT_SMEM>>>(trans, out);
}